// round 2
// baseline (speedup 1.0000x reference)
#include <cuda_runtime.h>
#include <math.h>

#define E_    32
#define TOPK  6
#define H_    2048
#define I_    1024
#define T_    2048
#define CAP_  768
#define SCALE_ 1.5f

// ---------------- scratch (device globals; no allocation allowed) ----------------
__device__ int   d_cnt[E_];
__device__ int   d_slot[T_ * TOPK];      // e*CAP_+pos, or -1 if dropped
__device__ float d_wt[T_ * TOPK];        // normalized * SCALE_
__device__ float d_xb[(size_t)E_ * CAP_ * H_];     // gathered tokens per expert
__device__ float d_inter[(size_t)E_ * CAP_ * I_];  // silu(g)*u per expert
__device__ float d_yb[(size_t)E_ * CAP_ * H_];     // expert outputs
__device__ float d_sinter[(size_t)T_ * I_];        // shared-expert intermediate

// ---------------- init ----------------
__global__ void init_kernel() {
    if (threadIdx.x < E_) d_cnt[threadIdx.x] = 0;
}

// ---------------- router: scores, top-k, slot assignment ----------------
__global__ void router_kernel(const float* __restrict__ x,
                              const float* __restrict__ gw,
                              const float* __restrict__ bias) {
    int t = blockIdx.x;
    const float4* h4 = (const float4*)(x + (size_t)t * H_);
    __shared__ float sc[E_];   // unbiased scores
    __shared__ float sb[E_];   // biased scores (for selection)
    int warp = threadIdx.x >> 5, lane = threadIdx.x & 31;

    for (int e = warp; e < E_; e += 4) {
        const float4* w4 = (const float4*)(gw + (size_t)e * H_);
        float s = 0.f;
        for (int i = lane; i < H_ / 4; i += 32) {
            float4 a = h4[i], b = w4[i];
            s += a.x * b.x + a.y * b.y + a.z * b.z + a.w * b.w;
        }
        #pragma unroll
        for (int o = 16; o > 0; o >>= 1) s += __shfl_xor_sync(0xffffffffu, s, o);
        if (lane == 0) {
            float sp = (s > 15.f) ? s : log1pf(expf(s));   // softplus
            sc[e] = sqrtf(sp);
        }
    }
    __syncthreads();
    if (threadIdx.x < E_) sb[threadIdx.x] = sc[threadIdx.x] + bias[threadIdx.x];
    __syncthreads();

    if (threadIdx.x == 0) {
        int   idx[TOPK];
        float wsum = 0.f;
        for (int k = 0; k < TOPK; k++) {
            int best = 0; float bv = -1e30f;
            for (int e = 0; e < E_; e++) {
                if (sb[e] > bv) { bv = sb[e]; best = e; }
            }
            idx[k] = best;
            sb[best] = -1e30f;
            wsum += sc[best];
        }
        float inv = SCALE_ / wsum;
        for (int k = 0; k < TOPK; k++) {
            int e = idx[k];
            int pos = atomicAdd(&d_cnt[e], 1);
            d_slot[t * TOPK + k] = (pos < CAP_) ? (e * CAP_ + pos) : -1;
            d_wt[t * TOPK + k]   = sc[e] * inv;
        }
    }
}

// ---------------- gather tokens into per-expert buffers ----------------
__global__ void gather_kernel(const float* __restrict__ x) {
    int s = blockIdx.x;             // 0 .. T*K-1
    int slot = d_slot[s];
    if (slot < 0) return;
    int t = s / TOPK;
    const float4* src = (const float4*)(x + (size_t)t * H_);
    float4* dst = (float4*)(d_xb + (size_t)slot * H_);
    for (int i = threadIdx.x; i < H_ / 4; i += blockDim.x) dst[i] = src[i];
}

// ---------------- gate+up GEMM fused with SwiGLU ----------------
// A[M,K] row-major, Bg/Bu[N,K] row-major; Out[M,N] = f(A Bg^T, A Bu^T)
// K = H_ (2048), N = I_ (1024). BM=128, BN=64, BK=16, 256 threads, 8x4 per thread x2.
template<bool ROUTED, bool CLAMP>
__global__ __launch_bounds__(256, 2)
void gateup_kernel(const float* __restrict__ Aext,
                   const float* __restrict__ Bg0,
                   const float* __restrict__ Bu0) {
    constexpr int Kd = H_;
    constexpr int Nd = I_;
    const int e = blockIdx.z;
    const float* A; const float* Bg; const float* Bu; float* Out; int M;
    if (ROUTED) {
        M   = min(d_cnt[e], CAP_);
        A   = d_xb    + (size_t)e * CAP_ * Kd;
        Bg  = Bg0     + (size_t)e * Nd * Kd;
        Bu  = Bu0     + (size_t)e * Nd * Kd;
        Out = d_inter + (size_t)e * CAP_ * Nd;
    } else {
        M = T_; A = Aext; Bg = Bg0; Bu = Bu0; Out = d_sinter;
    }
    const int m0 = blockIdx.x * 128;
    if (m0 >= M) return;
    const int n0 = blockIdx.y * 64;

    __shared__ float As[16][128];
    __shared__ float Bgs[16][64];
    __shared__ float Bus[16][64];

    const int tid = threadIdx.x;
    const int tm = (tid >> 4) * 8;
    const int tn = (tid & 15) * 4;

    float accg[8][4], accu[8][4];
    #pragma unroll
    for (int i = 0; i < 8; i++)
        #pragma unroll
        for (int j = 0; j < 4; j++) { accg[i][j] = 0.f; accu[i][j] = 0.f; }

    for (int kt = 0; kt < Kd; kt += 16) {
        // A tile: 128x16 = 512 float4, 2 per thread
        #pragma unroll
        for (int q = 0; q < 2; q++) {
            int f = tid * 2 + q;
            int ar = f >> 2, c4 = f & 3;
            int gr = m0 + ar;
            float4 v = make_float4(0.f, 0.f, 0.f, 0.f);
            if (gr < M) v = *(const float4*)(A + (size_t)gr * Kd + kt + c4 * 4);
            As[c4 * 4 + 0][ar] = v.x; As[c4 * 4 + 1][ar] = v.y;
            As[c4 * 4 + 2][ar] = v.z; As[c4 * 4 + 3][ar] = v.w;
        }
        // B tiles: 64x16 = 256 float4 each, 1 per thread
        {
            int ar = tid >> 2, c4 = tid & 3;
            size_t off = (size_t)(n0 + ar) * Kd + kt + c4 * 4;
            float4 vg = *(const float4*)(Bg + off);
            float4 vu = *(const float4*)(Bu + off);
            Bgs[c4 * 4 + 0][ar] = vg.x; Bgs[c4 * 4 + 1][ar] = vg.y;
            Bgs[c4 * 4 + 2][ar] = vg.z; Bgs[c4 * 4 + 3][ar] = vg.w;
            Bus[c4 * 4 + 0][ar] = vu.x; Bus[c4 * 4 + 1][ar] = vu.y;
            Bus[c4 * 4 + 2][ar] = vu.z; Bus[c4 * 4 + 3][ar] = vu.w;
        }
        __syncthreads();
        #pragma unroll
        for (int k = 0; k < 16; k++) {
            float4 a0 = *(const float4*)&As[k][tm];
            float4 a1 = *(const float4*)&As[k][tm + 4];
            float4 bg = *(const float4*)&Bgs[k][tn];
            float4 bu = *(const float4*)&Bus[k][tn];
            float a[8] = {a0.x, a0.y, a0.z, a0.w, a1.x, a1.y, a1.z, a1.w};
            float g[4] = {bg.x, bg.y, bg.z, bg.w};
            float u[4] = {bu.x, bu.y, bu.z, bu.w};
            #pragma unroll
            for (int i = 0; i < 8; i++)
                #pragma unroll
                for (int j = 0; j < 4; j++) {
                    accg[i][j] += a[i] * g[j];
                    accu[i][j] += a[i] * u[j];
                }
        }
        __syncthreads();
    }
    #pragma unroll
    for (int i = 0; i < 8; i++) {
        int gr = m0 + tm + i;
        if (gr >= M) continue;
        float v[4];
        #pragma unroll
        for (int j = 0; j < 4; j++) {
            float gg = accg[i][j], uu = accu[i][j];
            float sl = gg / (1.f + expf(-gg));     // silu
            float val = sl * uu;
            if (CLAMP) val = fminf(fmaxf(val, -10.f), 10.f);
            v[j] = val;
        }
        *(float4*)(Out + (size_t)gr * Nd + n0 + tn) = make_float4(v[0], v[1], v[2], v[3]);
    }
}

// ---------------- down-proj GEMM ----------------
// A[M,K] row-major (K=I_), B[N,K] row-major (N=H_); Out[M,N] = A B^T
// BM=128, BN=128, BK=16, 256 threads, 8x8 per thread (cols split tn / tn+64).
template<bool ROUTED>
__global__ __launch_bounds__(256, 2)
void down_kernel(const float* __restrict__ B0, float* __restrict__ OutExt) {
    constexpr int Kd = I_;
    constexpr int Nd = H_;
    const int e = blockIdx.z;
    const float* A; const float* B; float* Out; int M;
    if (ROUTED) {
        M   = min(d_cnt[e], CAP_);
        A   = d_inter + (size_t)e * CAP_ * Kd;
        B   = B0      + (size_t)e * Nd * Kd;
        Out = d_yb    + (size_t)e * CAP_ * Nd;
    } else {
        M = T_; A = d_sinter; B = B0; Out = OutExt;
    }
    const int m0 = blockIdx.x * 128;
    if (m0 >= M) return;
    const int n0 = blockIdx.y * 128;

    __shared__ float As[16][128];
    __shared__ float Bs[16][128];

    const int tid = threadIdx.x;
    const int tm = (tid >> 4) * 8;
    const int tn = (tid & 15) * 4;

    float acc[8][8];
    #pragma unroll
    for (int i = 0; i < 8; i++)
        #pragma unroll
        for (int j = 0; j < 8; j++) acc[i][j] = 0.f;

    for (int kt = 0; kt < Kd; kt += 16) {
        #pragma unroll
        for (int q = 0; q < 2; q++) {
            int f = tid * 2 + q;
            int ar = f >> 2, c4 = f & 3;
            int gr = m0 + ar;
            float4 v = make_float4(0.f, 0.f, 0.f, 0.f);
            if (gr < M) v = *(const float4*)(A + (size_t)gr * Kd + kt + c4 * 4);
            As[c4 * 4 + 0][ar] = v.x; As[c4 * 4 + 1][ar] = v.y;
            As[c4 * 4 + 2][ar] = v.z; As[c4 * 4 + 3][ar] = v.w;
        }
        #pragma unroll
        for (int q = 0; q < 2; q++) {
            int f = tid * 2 + q;
            int ar = f >> 2, c4 = f & 3;
            float4 v = *(const float4*)(B + (size_t)(n0 + ar) * Kd + kt + c4 * 4);
            Bs[c4 * 4 + 0][ar] = v.x; Bs[c4 * 4 + 1][ar] = v.y;
            Bs[c4 * 4 + 2][ar] = v.z; Bs[c4 * 4 + 3][ar] = v.w;
        }
        __syncthreads();
        #pragma unroll
        for (int k = 0; k < 16; k++) {
            float4 a0 = *(const float4*)&As[k][tm];
            float4 a1 = *(const float4*)&As[k][tm + 4];
            float4 b0 = *(const float4*)&Bs[k][tn];
            float4 b1 = *(const float4*)&Bs[k][tn + 64];
            float a[8] = {a0.x, a0.y, a0.z, a0.w, a1.x, a1.y, a1.z, a1.w};
            float b[8] = {b0.x, b0.y, b0.z, b0.w, b1.x, b1.y, b1.z, b1.w};
            #pragma unroll
            for (int i = 0; i < 8; i++)
                #pragma unroll
                for (int j = 0; j < 8; j++) acc[i][j] += a[i] * b[j];
        }
        __syncthreads();
    }
    #pragma unroll
    for (int i = 0; i < 8; i++) {
        int gr = m0 + tm + i;
        if (gr >= M) continue;
        float* orow = Out + (size_t)gr * Nd;
        *(float4*)(orow + n0 + tn)      = make_float4(acc[i][0], acc[i][1], acc[i][2], acc[i][3]);
        *(float4*)(orow + n0 + 64 + tn) = make_float4(acc[i][4], acc[i][5], acc[i][6], acc[i][7]);
    }
}

// ---------------- combine: out[t] = shared(out) + sum_k w * yb[slot] ----------------
__global__ void combine_kernel(float* __restrict__ out) {
    int t = blockIdx.x;
    __shared__ int   ss[TOPK];
    __shared__ float sw[TOPK];
    if (threadIdx.x < TOPK) {
        ss[threadIdx.x] = d_slot[t * TOPK + threadIdx.x];
        sw[threadIdx.x] = d_wt[t * TOPK + threadIdx.x];
    }
    __syncthreads();
    float4* orow = (float4*)(out + (size_t)t * H_);
    for (int i = threadIdx.x; i < H_ / 4; i += blockDim.x) {
        float4 o = orow[i];
        #pragma unroll
        for (int k = 0; k < TOPK; k++) {
            int slot = ss[k];
            if (slot < 0) continue;
            float w = sw[k];
            float4 y = ((const float4*)(d_yb + (size_t)slot * H_))[i];
            o.x += w * y.x; o.y += w * y.y; o.z += w * y.z; o.w += w * y.w;
        }
        orow[i] = o;
    }
}

// ---------------- launch ----------------
extern "C" void kernel_launch(void* const* d_in, const int* in_sizes, int n_in,
                              void* d_out, int out_size) {
    const float* x      = (const float*)d_in[0];
    const float* gate_w = (const float*)d_in[1];
    const float* bias   = (const float*)d_in[2];
    const float* w_gate = (const float*)d_in[3];
    const float* w_up   = (const float*)d_in[4];
    const float* w_down = (const float*)d_in[5];
    const float* sg     = (const float*)d_in[6];
    const float* su     = (const float*)d_in[7];
    const float* sd     = (const float*)d_in[8];
    float* out = (float*)d_out;

    init_kernel<<<1, 32>>>();
    router_kernel<<<T_, 128>>>(x, gate_w, bias);
    gather_kernel<<<T_ * TOPK, 128>>>(x);

    // routed experts: gate/up + SwiGLU, then down
    gateup_kernel<true, false><<<dim3(CAP_ / 128, I_ / 64, E_), 256>>>(nullptr, w_gate, w_up);
    down_kernel<true><<<dim3(CAP_ / 128, H_ / 128, E_), 256>>>(w_down, nullptr);

    // shared expert: gate/up with clamp, then down writes d_out
    gateup_kernel<false, true><<<dim3(T_ / 128, I_ / 64, 1), 256>>>(x, sg, su);
    down_kernel<false><<<dim3(T_ / 128, H_ / 128, 1), 256>>>(sd, out);

    // combine routed contributions into d_out (deterministic, no atomics)
    combine_kernel<<<T_, 256>>>(out);
}

// round 6
// speedup vs baseline: 5.3020x; 5.3020x over previous
#include <cuda_runtime.h>
#include <math.h>
#include <stdint.h>

#define E_    32
#define TOPK  6
#define H_    2048
#define I_    1024
#define T_    2048
#define CAP_  768
#define SCALE_ 1.5f

// ---------------- scratch (device globals; no allocation allowed) ----------------
__device__ int   d_cnt[E_];
__device__ int   d_src[E_ * CAP_];        // slot -> token
__device__ int   d_slot[T_ * TOPK];       // e*CAP_+pos, or -1 if dropped
__device__ float d_wt[T_ * TOPK];         // normalized * SCALE_
__device__ float d_g[(size_t)E_ * CAP_ * I_];       // routed gate-proj raw output
__device__ float d_gsh[(size_t)T_ * I_];            // shared gate-proj raw output
__device__ float d_inter[(size_t)E_ * CAP_ * I_];   // silu(g)*u per expert
__device__ float d_sinter[(size_t)T_ * I_];         // shared-expert intermediate
__device__ float d_yb[(size_t)E_ * CAP_ * H_];      // expert outputs

// =================== portable PTX helpers (compute_103-safe, sm_80+) ===================
__device__ __forceinline__ uint32_t smem_u32(const void* p) {
    uint32_t a;
    asm("{ .reg .u64 t; cvta.to.shared.u64 t, %1; cvt.u32.u64 %0, t; }" : "=r"(a) : "l"(p));
    return a;
}
__device__ __forceinline__ uint32_t tf32r(float f) {
    uint32_t r; asm("cvt.rna.tf32.f32 %0, %1;" : "=r"(r) : "f"(f)); return r;
}
__device__ __forceinline__ void cp16(uint32_t saddr, const void* gaddr, bool v) {
    int sz = v ? 16 : 0;
    asm volatile("cp.async.ca.shared.global [%0], [%1], 16, %2;"
                 :: "r"(saddr), "l"(gaddr), "r"(sz) : "memory");
}
#define CP_COMMIT() asm volatile("cp.async.commit_group;" ::: "memory")
#define CP_WAIT1()  asm volatile("cp.async.wait_group 1;" ::: "memory")
#define CP_WAIT0()  asm volatile("cp.async.wait_group 0;" ::: "memory")

__device__ __forceinline__ void mma_tf32(float* c, const uint32_t* a, const uint32_t* b) {
    asm volatile(
        "mma.sync.aligned.m16n8k8.row.col.f32.tf32.tf32.f32 "
        "{%0,%1,%2,%3}, {%4,%5,%6,%7}, {%8,%9}, {%0,%1,%2,%3};"
        : "+f"(c[0]), "+f"(c[1]), "+f"(c[2]), "+f"(c[3])
        : "r"(a[0]), "r"(a[1]), "r"(a[2]), "r"(a[3]), "r"(b[0]), "r"(b[1]));
}

// ---------------- init ----------------
__global__ void init_kernel() {
    if (threadIdx.x < E_) d_cnt[threadIdx.x] = 0;
}

// ---------------- router ----------------
__global__ void router_kernel(const float* __restrict__ x,
                              const float* __restrict__ gw,
                              const float* __restrict__ bias) {
    int t = blockIdx.x;
    const float4* h4 = (const float4*)(x + (size_t)t * H_);
    __shared__ float sc[E_];
    __shared__ float sb[E_];
    int warp = threadIdx.x >> 5, lane = threadIdx.x & 31;

    for (int e = warp; e < E_; e += 4) {
        const float4* w4 = (const float4*)(gw + (size_t)e * H_);
        float s = 0.f;
        for (int i = lane; i < H_ / 4; i += 32) {
            float4 a = h4[i], b = w4[i];
            s += a.x * b.x + a.y * b.y + a.z * b.z + a.w * b.w;
        }
        #pragma unroll
        for (int o = 16; o > 0; o >>= 1) s += __shfl_xor_sync(0xffffffffu, s, o);
        if (lane == 0) {
            float sp = (s > 15.f) ? s : log1pf(expf(s));
            sc[e] = sqrtf(sp);
        }
    }
    __syncthreads();
    if (threadIdx.x < E_) sb[threadIdx.x] = sc[threadIdx.x] + bias[threadIdx.x];
    __syncthreads();

    if (threadIdx.x == 0) {
        int   idx[TOPK];
        float wsum = 0.f;
        for (int k = 0; k < TOPK; k++) {
            int best = 0; float bv = -1e30f;
            for (int e = 0; e < E_; e++)
                if (sb[e] > bv) { bv = sb[e]; best = e; }
            idx[k] = best;
            sb[best] = -1e30f;
            wsum += sc[best];
        }
        float inv = SCALE_ / wsum;
        for (int k = 0; k < TOPK; k++) {
            int e = idx[k];
            int pos = atomicAdd(&d_cnt[e], 1);
            if (pos < CAP_) {
                d_slot[t * TOPK + k] = e * CAP_ + pos;
                d_src[e * CAP_ + pos] = t;
            } else {
                d_slot[t * TOPK + k] = -1;
            }
            d_wt[t * TOPK + k] = sc[e] * inv;
        }
    }
}

// =================== tf32 mma.sync GEMM ===================
// C[M,N] = A[M,K] @ B[N,K]^T per expert (z). z==E_ -> shared expert.
// MODE 0: gate pass  (A = gathered x, B = w_gate/sg, C = d_g/d_gsh, raw store)
// MODE 1: up pass    (A = gathered x, B = w_up/su,   C = d_inter/d_sinter, silu(G)*U [+clamp if shared])
// MODE 2: down pass  (A = d_inter/d_sinter, B = w_down/sd, C = d_yb/out)
// Tiles: CTA 128x128x32, 8 warps (2 m x 4 n), warp 64x32, mma m16n8k8.
// smem: [row][k] pitch 36 floats, double-buffered, cp.async-fed.

#define PITCH 36
#define STAGE_FLOATS (128 * PITCH)            // 4608 per operand
#define STAGE_BYTES  (2 * STAGE_FLOATS * 4)   // 36864 (A + B)
#define SMEM_GEMM    (2 * STAGE_BYTES)        // 73728

template<int MODE>
__global__ __launch_bounds__(256, 2)
void gemm_tc(const float* __restrict__ x,
             const float* __restrict__ wR,    // routed weights [E, Nd, Kd]
             const float* __restrict__ wS,    // shared weights [Nd, Kd]
             float* __restrict__ out)
{
    constexpr int Kd = (MODE == 2) ? I_ : H_;
    constexpr int Nd = (MODE == 2) ? H_ : I_;
    constexpr int C  = Kd / 32;

    const int e = blockIdx.z;
    const bool sh = (e == E_);
    const int M = sh ? T_ : min(d_cnt[e], CAP_);
    const int m0 = blockIdx.y * 128;
    if (m0 >= M) return;
    const int n0 = blockIdx.x * 128;

    const float* A; const float* B; float* Cp; const float* G = nullptr;
    const int* src = nullptr;
    if (MODE == 0) {
        A = x;
        B = sh ? wS : wR + (size_t)e * Nd * Kd;
        Cp = sh ? d_gsh : d_g + (size_t)e * CAP_ * Nd;
        if (!sh) src = d_src + e * CAP_;
    } else if (MODE == 1) {
        A = x;
        B = sh ? wS : wR + (size_t)e * Nd * Kd;
        Cp = sh ? d_sinter : d_inter + (size_t)e * CAP_ * Nd;
        G  = sh ? d_gsh : d_g + (size_t)e * CAP_ * Nd;
        if (!sh) src = d_src + e * CAP_;
    } else {
        A = sh ? d_sinter : d_inter + (size_t)e * CAP_ * Kd;
        B = sh ? wS : wR + (size_t)e * Nd * Kd;
        Cp = sh ? out : d_yb + (size_t)e * CAP_ * Nd;
    }

    extern __shared__ char dsm[];
    __shared__ int srow[128];

    const int tid = threadIdx.x;
    const int wid = tid >> 5, lane = tid & 31;
    const int wr = wid >> 2, wc = wid & 3;       // warp 2x4 grid
    const int g = lane >> 2, tig = lane & 3;

    if (MODE < 2 && !sh) {
        if (tid < 128) srow[tid] = (m0 + tid < M) ? src[m0 + tid] : 0;
    }
    __syncthreads();

    const uint32_t smem_base = smem_u32(dsm);

    // ---- chunk loader: A and B tiles (128 rows x 32 k) via cp.async ----
    auto load_chunk = [&](int kt, int s) {
        const uint32_t sa = smem_base + (uint32_t)s * STAGE_BYTES;
        const uint32_t sbB = sa + STAGE_FLOATS * 4;
        #pragma unroll
        for (int q = 0; q < 4; q++) {
            int idx = tid + q * 256;
            int row = idx >> 3, c4 = idx & 7;
            // A
            int gr = m0 + row;
            bool v = gr < M;
            const float* gp;
            if (MODE < 2 && !sh) gp = x + (size_t)srow[row] * Kd + kt + c4 * 4;
            else                 gp = A + (size_t)(v ? gr : m0) * Kd + kt + c4 * 4;
            cp16(sa + (uint32_t)(row * PITCH + c4 * 4) * 4, gp, v);
            // B
            const float* gb = B + (size_t)(n0 + row) * Kd + kt + c4 * 4;
            cp16(sbB + (uint32_t)(row * PITCH + c4 * 4) * 4, gb, true);
        }
    };

    float acc[4][4][4];
    #pragma unroll
    for (int i = 0; i < 4; i++)
        #pragma unroll
        for (int j = 0; j < 4; j++)
            #pragma unroll
            for (int r = 0; r < 4; r++) acc[i][j][r] = 0.f;

    load_chunk(0, 0);
    CP_COMMIT();

    for (int c = 0; c < C; c++) {
        const int s = c & 1;
        if (c + 1 < C) { load_chunk((c + 1) * 32, s ^ 1); CP_COMMIT(); CP_WAIT1(); }
        else           { CP_WAIT0(); }
        __syncthreads();

        const float* As = (const float*)(dsm + (size_t)s * STAGE_BYTES);
        const float* Bs = As + STAGE_FLOATS;
        #pragma unroll
        for (int ks = 0; ks < 4; ks++) {
            uint32_t a[4][4], b[4][2];
            #pragma unroll
            for (int mt = 0; mt < 4; mt++) {
                int base = (wr * 64 + mt * 16 + g) * PITCH + ks * 8 + tig;
                a[mt][0] = tf32r(As[base]);
                a[mt][1] = tf32r(As[base + 8 * PITCH]);
                a[mt][2] = tf32r(As[base + 4]);
                a[mt][3] = tf32r(As[base + 8 * PITCH + 4]);
            }
            #pragma unroll
            for (int nt = 0; nt < 4; nt++) {
                int base = (wc * 32 + nt * 8 + g) * PITCH + ks * 8 + tig;
                b[nt][0] = tf32r(Bs[base]);
                b[nt][1] = tf32r(Bs[base + 4]);
            }
            #pragma unroll
            for (int mt = 0; mt < 4; mt++)
                #pragma unroll
                for (int nt = 0; nt < 4; nt++)
                    mma_tf32(acc[mt][nt], a[mt], b[nt]);
        }
        __syncthreads();
    }

    // ---- epilogue ----
    #pragma unroll
    for (int mt = 0; mt < 4; mt++) {
        #pragma unroll
        for (int nt = 0; nt < 4; nt++) {
            int r0 = m0 + wr * 64 + mt * 16 + g;
            int col = n0 + wc * 32 + nt * 8 + 2 * tig;
            #pragma unroll
            for (int h = 0; h < 2; h++) {
                int r = r0 + 8 * h;
                if (r >= M) continue;
                float v0 = acc[mt][nt][2 * h + 0];
                float v1 = acc[mt][nt][2 * h + 1];
                size_t off = (size_t)r * Nd + col;
                if (MODE == 0) {
                    *(float2*)(Cp + off) = make_float2(v0, v1);
                } else if (MODE == 1) {
                    float2 gg = *(const float2*)(G + off);
                    float s0 = gg.x / (1.f + expf(-gg.x)) * v0;
                    float s1 = gg.y / (1.f + expf(-gg.y)) * v1;
                    if (sh) {
                        s0 = fminf(fmaxf(s0, -10.f), 10.f);
                        s1 = fminf(fmaxf(s1, -10.f), 10.f);
                    }
                    *(float2*)(Cp + off) = make_float2(s0, s1);
                } else {
                    *(float2*)(Cp + off) = make_float2(v0, v1);
                }
            }
        }
    }
}

// ---------------- combine: out[t] = shared(out) + sum_k w * yb[slot] ----------------
__global__ void combine_kernel(float* __restrict__ out) {
    int t = blockIdx.x;
    __shared__ int   ss[TOPK];
    __shared__ float sw[TOPK];
    if (threadIdx.x < TOPK) {
        ss[threadIdx.x] = d_slot[t * TOPK + threadIdx.x];
        sw[threadIdx.x] = d_wt[t * TOPK + threadIdx.x];
    }
    __syncthreads();
    float4* orow = (float4*)(out + (size_t)t * H_);
    for (int i = threadIdx.x; i < H_ / 4; i += blockDim.x) {
        float4 o = orow[i];
        #pragma unroll
        for (int k = 0; k < TOPK; k++) {
            int slot = ss[k];
            if (slot < 0) continue;
            float w = sw[k];
            float4 y = ((const float4*)(d_yb + (size_t)slot * H_))[i];
            o.x += w * y.x; o.y += w * y.y; o.z += w * y.z; o.w += w * y.w;
        }
        orow[i] = o;
    }
}

// ---------------- launch ----------------
extern "C" void kernel_launch(void* const* d_in, const int* in_sizes, int n_in,
                              void* d_out, int out_size) {
    const float* x      = (const float*)d_in[0];
    const float* gate_w = (const float*)d_in[1];
    const float* bias   = (const float*)d_in[2];
    const float* w_gate = (const float*)d_in[3];
    const float* w_up   = (const float*)d_in[4];
    const float* w_down = (const float*)d_in[5];
    const float* sg     = (const float*)d_in[6];
    const float* su     = (const float*)d_in[7];
    const float* sd     = (const float*)d_in[8];
    float* out = (float*)d_out;

    cudaFuncSetAttribute(gemm_tc<0>, cudaFuncAttributeMaxDynamicSharedMemorySize, SMEM_GEMM);
    cudaFuncSetAttribute(gemm_tc<1>, cudaFuncAttributeMaxDynamicSharedMemorySize, SMEM_GEMM);
    cudaFuncSetAttribute(gemm_tc<2>, cudaFuncAttributeMaxDynamicSharedMemorySize, SMEM_GEMM);

    init_kernel<<<1, 32>>>();
    router_kernel<<<T_, 128>>>(x, gate_w, bias);

    // gate pass, up pass (fused SwiGLU), down pass — routed e=0..31 + shared e=32
    gemm_tc<0><<<dim3(I_ / 128, 16, E_ + 1), 256, SMEM_GEMM>>>(x, w_gate, sg, out);
    gemm_tc<1><<<dim3(I_ / 128, 16, E_ + 1), 256, SMEM_GEMM>>>(x, w_up,   su, out);
    gemm_tc<2><<<dim3(H_ / 128, 16, E_ + 1), 256, SMEM_GEMM>>>(x, w_down, sd, out);

    combine_kernel<<<T_, 256>>>(out);
}